// round 4
// baseline (speedup 1.0000x reference)
#include <cuda_runtime.h>

// y[t, f] = x[t, f] * w[f] + b[f]
// x: [8192, 4096] f32, w/b: [4096] f32, out: [8192, 4096] f32
// Compulsory traffic: 268.4 MB. HBM-wall kernel; optimize burst structure.
// Each thread: 8 rows x 1 float4 column.
//   - 8 front-batched independent LDG.128 (long read burst, MLP=8)
//   - 8 batched STG.128 (long write burst)
//   - .cs streaming hints on x/out; w/b stay cached (16 KB each)

static constexpr int TOKENS = 8192;
static constexpr int FEATURES = 4096;
static constexpr int F4_PER_ROW = FEATURES / 4;               // 1024
static constexpr int ROWS_PER_THREAD = 8;
static constexpr int TOTAL_GROUPS = (TOKENS / ROWS_PER_THREAD) * F4_PER_ROW;  // 1,048,576

__global__ void __launch_bounds__(256) one_to_one_kernel(
    const float4* __restrict__ x,
    const float4* __restrict__ w,
    const float4* __restrict__ b,
    float4* __restrict__ out)
{
    int i = blockIdx.x * blockDim.x + threadIdx.x;
    if (i >= TOTAL_GROUPS) return;

    int c  = i & (F4_PER_ROW - 1);     // column (float4 units)
    int rg = i >> 10;                  // row group of 8
    int base = rg * (ROWS_PER_THREAD * F4_PER_ROW) + c;

    float4 xv[ROWS_PER_THREAD];
#pragma unroll
    for (int r = 0; r < ROWS_PER_THREAD; r++)
        xv[r] = __ldcs(&x[base + r * F4_PER_ROW]);

    float4 wv = __ldg(&w[c]);
    float4 bv = __ldg(&b[c]);

    float4 rv[ROWS_PER_THREAD];
#pragma unroll
    for (int r = 0; r < ROWS_PER_THREAD; r++) {
        rv[r].x = fmaf(xv[r].x, wv.x, bv.x);
        rv[r].y = fmaf(xv[r].y, wv.y, bv.y);
        rv[r].z = fmaf(xv[r].z, wv.z, bv.z);
        rv[r].w = fmaf(xv[r].w, wv.w, bv.w);
    }

#pragma unroll
    for (int r = 0; r < ROWS_PER_THREAD; r++)
        __stcs(&out[base + r * F4_PER_ROW], rv[r]);
}

extern "C" void kernel_launch(void* const* d_in, const int* in_sizes, int n_in,
                              void* d_out, int out_size)
{
    const float4* x = (const float4*)d_in[0];
    const float4* w = (const float4*)d_in[1];
    const float4* b = (const float4*)d_in[2];
    float4* out = (float4*)d_out;

    const int threads = 256;
    const int blocks = (TOTAL_GROUPS + threads - 1) / threads;  // 4096
    one_to_one_kernel<<<blocks, threads>>>(x, w, b, out);
}